// round 10
// baseline (speedup 1.0000x reference)
#include <cuda_runtime.h>

// Problem constants
#define IMG_H 512
#define IMG_W 512
#define NIMG  64
#define NPIX  (NIMG * IMG_H * IMG_W)   // 16,777,216

#define TILE_W   32
#define TILE_H   64
#define HALO     5
#define SW_H     74          // TILE_H + 2*HALO
#define PAD_L    8           // left pad (>= HALO, quad aligned)
#define XY_W     48          // logical strip width in packed elems (12 quads)
#define XY_S     50          // PADDED row stride in packed elems (400B: kills bank aliasing)
#define NTHREADS 512
#define GRID_X   (IMG_W / TILE_W)   // 16
#define GRID_Y   (IMG_H / TILE_H)   // 8
#define NBLOCKS  (GRID_X * GRID_Y * NIMG)   // 8192

// SMEM layout (bytes):
//  xy  : 74*50*8  = 29600   packed (x,y) inputs, padded stride
//  mid : 74*32*16 = 37888   {(mu1,mu2), (x2+y2, xy)}, column-swizzled
#define XY_BYTES   (SW_H * XY_S * 8)
#define SMEM_BYTES (XY_BYTES + SW_H * TILE_W * 16)   // 67,488 -> 3 CTAs/SM

// mid column swizzle: logical col c -> physical (c&3)*8 + (c>>2)  (bijection on 0..31)
#define MIDP(c) ((((c) & 3) << 3) + ((c) >> 2))

// Separable Gaussian (sigma=1.5, 11 taps), normalized.
#define W0 0.00102838f
#define W1 0.00759876f
#define W2 0.03600077f
#define W3 0.10936060f
#define W4 0.21300553f
#define W5 0.26601172f
__device__ constexpr float GW[11] = {W0, W1, W2, W3, W4, W5, W4, W3, W2, W1, W0};
#define GPI(t) ((t) < 6 ? (t) : 10 - (t))

typedef unsigned long long ull;

__device__ __forceinline__ ull pack2(float lo, float hi) {
    ull d;
    asm("mov.b64 %0, {%1, %2};" : "=l"(d) : "r"(__float_as_uint(lo)), "r"(__float_as_uint(hi)));
    return d;
}
__device__ __forceinline__ void unpack2(ull v, float& lo, float& hi) {
    unsigned r0, r1;
    asm("mov.b64 {%0, %1}, %2;" : "=r"(r0), "=r"(r1) : "l"(v));
    lo = __uint_as_float(r0); hi = __uint_as_float(r1);
}
__device__ __forceinline__ ull fma2(ull a, ull b, ull c) {
    ull d;
    asm("fma.rn.f32x2 %0, %1, %2, %3;" : "=l"(d) : "l"(a), "l"(b), "l"(c));
    return d;
}

__device__ float g_partials[NBLOCKS];
__device__ int   g_count = 0;

extern __shared__ char smem_raw[];

__global__ __launch_bounds__(NTHREADS, 3)
void ssim_fused_kernel(const float* __restrict__ img1, const float* __restrict__ img2,
                       float* __restrict__ out) {
    ull*        xy   = (ull*)smem_raw;                      // 74 x 50 packed (x,y)
    ulonglong2* midm = (ulonglong2*)(smem_raw + XY_BYTES);  // 74 x 32, col-swizzled

    const int tid = threadIdx.x;
    const int img = blockIdx.z;
    const int r0  = blockIdx.y * TILE_H;
    const int c0  = blockIdx.x * TILE_W;
    const float* p1 = img1 + (size_t)img * (IMG_H * IMG_W);
    const float* p2 = img2 + (size_t)img * (IMG_H * IMG_W);

    // Packed Gaussian weight pairs (6 distinct by symmetry)
    ull gp[6];
    gp[0] = pack2(W0, W0); gp[1] = pack2(W1, W1); gp[2] = pack2(W2, W2);
    gp[3] = pack2(W3, W3); gp[4] = pack2(W4, W4); gp[5] = pack2(W5, W5);

    // ---- Load halo strip: unit = (row, quad of 4 cols) ----
    // Strip covers global cols [c0-8, c0+40); every quad uniformly valid or OOB.
    for (int u = tid; u < SW_H * (XY_W / 4); u += NTHREADS) {
        int r = u / (XY_W / 4);
        int q = u - r * (XY_W / 4);
        int gr = r0 + r - HALO;
        int gc = c0 - PAD_L + q * 4;
        float4 vx = make_float4(0.f, 0.f, 0.f, 0.f);
        float4 vy = vx;
        if (gr >= 0 && gr < IMG_H && gc >= 0 && gc + 3 < IMG_W) {
            vx = *(const float4*)(p1 + (size_t)gr * IMG_W + gc);
            vy = *(const float4*)(p2 + (size_t)gr * IMG_W + gc);
        }
        ulonglong2* dst = (ulonglong2*)(xy + r * XY_S + q * 4);
        dst[0] = make_ulonglong2(pack2(vx.x, vy.x), pack2(vx.y, vy.y));
        dst[1] = make_ulonglong2(pack2(vx.z, vy.z), pack2(vx.w, vy.w));
    }
    __syncthreads();

    // ---- Horizontal pass: unit = (row, 4 output cols); 74*8 = 592 units ----
    for (int unit = tid; unit < SW_H * (TILE_W / 4); unit += NTHREADS) {
        int row = unit >> 3;
        int tq  = unit & 7;          // which 4-col group
        int cb  = tq * 4;

        // Needed input col n lives at smem col n + (PAD_L - HALO) = n + 3.
        // Load 16 packed starting at smem col cb+2 (16B aligned); use v[1..14].
        ull v[16];
        const ulonglong2* vr = (const ulonglong2*)(xy + row * XY_S + cb + 2);
        #pragma unroll
        for (int i = 0; i < 8; i++) {
            ulonglong2 t = vr[i];
            v[2 * i]     = t.x;
            v[2 * i + 1] = t.y;
        }

        // Sweep A: packed (mu1,mu2) conv
        ull mu[4] = {0, 0, 0, 0};
        #pragma unroll
        for (int k = 1; k < 15; k++) {
            #pragma unroll
            for (int j = 0; j < 4; j++) {
                const int t = k - 1 - j;
                if (t >= 0 && t < 11)
                    mu[j] = fma2(gp[GPI(t)], v[k], mu[j]);
            }
        }
        // Sweep B: packed (z, xy) conv where z = x^2 + y^2
        ull sz[4] = {0, 0, 0, 0};
        #pragma unroll
        for (int k = 1; k < 15; k++) {
            float x, y;
            unpack2(v[k], x, y);
            const float e = x * y;
            const float z = fmaf(x, x, y * y);
            const ull   w = pack2(z, e);
            #pragma unroll
            for (int j = 0; j < 4; j++) {
                const int t = k - 1 - j;
                if (t >= 0 && t < 11)
                    sz[j] = fma2(gp[GPI(t)], w, sz[j]);
            }
        }
        // Swizzled stores: logical col cb+j -> physical j*8 + tq.
        // Fixed-j store across a warp: 8 threads x 16B contiguous per row -> no conflicts.
        #pragma unroll
        for (int j = 0; j < 4; j++)
            midm[row * TILE_W + j * 8 + tq] = make_ulonglong2(mu[j], sz[j]);
    }
    __syncthreads();

    // ---- Vertical pass + SSIM: 16 groups x 32 cols, 4 rows/thread ----
    float local = 0.f;
    const int col  = tid & (TILE_W - 1);
    const int pcol = MIDP(col);          // physical column (bijection; warp covers row fully)
    const int rb   = (tid >> 5) * 4;

    const float C1 = 0.0001f;
    const float C2 = 0.0009f;

    {
        ull amu[4] = {0, 0, 0, 0};
        ull asz[4] = {0, 0, 0, 0};

        #pragma unroll
        for (int k = 0; k < 14; k++) {
            const ulonglong2 m = midm[(rb + k) * TILE_W + pcol];
            #pragma unroll
            for (int j = 0; j < 4; j++) {
                const int t = k - j;
                if (t >= 0 && t < 11) {
                    const ull gpt = gp[GPI(t)];
                    amu[j] = fma2(gpt, m.x, amu[j]);
                    asz[j] = fma2(gpt, m.y, asz[j]);
                }
            }
        }

        #pragma unroll
        for (int j = 0; j < 4; j++) {
            float mu1, mu2, z, exy;
            unpack2(amu[j], mu1, mu2);
            unpack2(asz[j], z, exy);
            const float S   = fmaf(mu1, mu1, mu2 * mu2);   // mu1^2 + mu2^2
            const float P   = mu1 * mu2;
            const float s12 = exy - P;                     // sigma12
            const float sig = z - S;                       // sigma1^2 + sigma2^2
            const float num = (2.f * P + C1) * (2.f * s12 + C2);
            const float den = (S + C1) * (sig + C2);
            local += __fdividef(num, den);
        }
    }

    // ---- Block reduction (fixed order -> deterministic) ----
    #pragma unroll
    for (int off = 16; off > 0; off >>= 1)
        local += __shfl_xor_sync(0xffffffffu, local, off);

    __shared__ float wsum[NTHREADS / 32];
    __shared__ int   s_last;
    if ((tid & 31) == 0) wsum[tid >> 5] = local;
    __syncthreads();
    if (tid == 0) {
        float s = 0.f;
        #pragma unroll
        for (int w = 0; w < NTHREADS / 32; w++) s += wsum[w];
        int bid = (blockIdx.z * gridDim.y + blockIdx.y) * gridDim.x + blockIdx.x;
        g_partials[bid] = s;
        __threadfence();
        int old = atomicAdd(&g_count, 1);
        s_last = (old == NBLOCKS - 1);
    }
    __syncthreads();

    // ---- Last block: deterministic final reduction in fp64, reset counter ----
    if (s_last) {
        __threadfence();
        __shared__ double dsh[NTHREADS / 32];
        double acc = 0.0;
        const int per = NBLOCKS / NTHREADS;   // 16
        for (int i = 0; i < per; i++)
            acc += (double)g_partials[tid * per + i];
        #pragma unroll
        for (int off = 16; off > 0; off >>= 1)
            acc += __shfl_xor_sync(0xffffffffu, acc, off);
        if ((tid & 31) == 0) dsh[tid >> 5] = acc;
        __syncthreads();
        if (tid == 0) {
            double s = 0.0;
            #pragma unroll
            for (int w = 0; w < NTHREADS / 32; w++) s += dsh[w];
            out[0] = (float)(1.0 - s * (1.0 / (double)NPIX));
            g_count = 0;   // reset for next graph replay
        }
    }
}

extern "C" void kernel_launch(void* const* d_in, const int* in_sizes, int n_in,
                              void* d_out, int out_size) {
    const float* pred   = (const float*)d_in[0];
    const float* target = (const float*)d_in[1];
    float* out = (float*)d_out;

    cudaFuncSetAttribute(ssim_fused_kernel,
                         cudaFuncAttributeMaxDynamicSharedMemorySize, SMEM_BYTES);

    dim3 grid(GRID_X, GRID_Y, NIMG);   // (16, 8, 64)
    ssim_fused_kernel<<<grid, NTHREADS, SMEM_BYTES>>>(pred, target, out);
}